// round 13
// baseline (speedup 1.0000x reference)
#include <cuda_runtime.h>
#include <cstdint>
#include <math.h>

#define TT   16
#define MTOT 2048
#define HH   2048
#define DIN  1024
#define DOUT 1024

#define NTHR 512
#define PTHR 512
#define KCB  128          // int8 k per super-chunk (one 128B swizzle row)

// ---------------- static device scratch ----------------
__device__ __align__(1024) int8_t g_A0 [(size_t)MTOT * DIN];
__device__ __align__(1024) int8_t g_s0 [(size_t)MTOT * HH];
__device__ __align__(1024) int8_t g_s1 [(size_t)MTOT * HH];
__device__ __align__(1024) int8_t g_W0q[(size_t)HH   * 3 * DIN];
__device__ __align__(1024) int8_t g_W1q[(size_t)HH   * 3 * HH];
__device__ __align__(1024) int8_t g_Woq[(size_t)DOUT * 3 * HH];

// ---------------- helpers ----------------
__device__ __forceinline__ uint32_t smem_u32(const void* p) {
    uint32_t a;
    asm("{ .reg .u64 t; cvta.to.shared.u64 t, %1; cvt.u32.u64 %0, t; }" : "=r"(a) : "l"(p));
    return a;
}
__device__ __forceinline__ void cp16(uint32_t dst, const void* src) {
    asm volatile("cp.async.cg.shared.global [%0], [%1], 16;" :: "r"(dst), "l"(src));
}
#define CP_COMMIT() asm volatile("cp.async.commit_group;" ::: "memory")
#define CP_WAIT(n)  asm volatile("cp.async.wait_group %0;" :: "n"(n) : "memory")
#define SWZ(off) ((off) ^ (((off) >> 3) & 0x70))

__device__ __forceinline__ void ldsm4(uint32_t& r0, uint32_t& r1, uint32_t& r2, uint32_t& r3,
                                      uint32_t addr) {
    asm volatile("ldmatrix.sync.aligned.m8n8.x4.shared.b16 {%0,%1,%2,%3}, [%4];"
                 : "=r"(r0), "=r"(r1), "=r"(r2), "=r"(r3) : "r"(addr));
}
__device__ __forceinline__ void imma(int* d, const uint32_t* a, uint32_t b0, uint32_t b1) {
    asm volatile(
        "mma.sync.aligned.m16n8k32.row.col.s32.s8.s8.s32 "
        "{%0,%1,%2,%3}, {%4,%5,%6,%7}, {%8,%9}, {%0,%1,%2,%3};"
        : "+r"(d[0]), "+r"(d[1]), "+r"(d[2]), "+r"(d[3])
        : "r"(a[0]), "r"(a[1]), "r"(a[2]), "r"(a[3]), "r"(b0), "r"(b1));
}

// exact 3-limb int8 split of round(w*2^27): l2*2^16 + l1*2^8 + l0
__device__ __forceinline__ void quant_range(const float* __restrict__ W,
                                            int8_t* __restrict__ Wq,
                                            int Nw, int K, int eblk, int nblk) {
    const int total4 = (Nw * K) >> 2;
    const int KP = 3 * K;
    const int bsz = blockDim.x;
    for (int i4 = eblk * bsz + threadIdx.x; i4 < total4; i4 += nblk * bsz) {
        int idx = i4 << 2;
        int n = idx / K, k = idx - n * K;
        float4 w4 = *(const float4*)(W + idx);
        float wv[4] = {w4.x, w4.y, w4.z, w4.w};
        char l2v[4], l1v[4], l0v[4];
#pragma unroll
        for (int j = 0; j < 4; ++j) {
            long long wi = llrintf(wv[j] * 134217728.0f);   // 2^27
            int l0 = (int)((wi + 128) & 255) - 128;  wi = (wi - l0) >> 8;
            int l1 = (int)((wi + 128) & 255) - 128;  wi = (wi - l1) >> 8;
            l2v[j] = (char)wi; l1v[j] = (char)l1; l0v[j] = (char)l0;
        }
        size_t base = (size_t)n * KP + k;
        *(char4*)(Wq + base)         = make_char4(l2v[0], l2v[1], l2v[2], l2v[3]);
        *(char4*)(Wq + base + K)     = make_char4(l1v[0], l1v[1], l1v[2], l1v[3]);
        *(char4*)(Wq + base + 2 * K) = make_char4(l0v[0], l0v[1], l0v[2], l0v[3]);
    }
}

// ---------------- prep: conv_in (blocks 0..127) + quant W0 (blocks 128..183) ----------------
__global__ __launch_bounds__(PTHR)
void prep_kernel(const float* __restrict__ in, int8_t* __restrict__ A,
                 const float* __restrict__ W0, int8_t* __restrict__ W0q)
{
    const int bid = blockIdx.x;
    const int tid = threadIdx.x;
    if (bid >= 128) {
        quant_range(W0, W0q, HH, DIN, bid - 128, 56);
        return;
    }
    __shared__ int8_t sbuf[DIN * TT];   // [k][t], 16KB
    const int b = bid;
    const float4* src = (const float4*)(in + (size_t)b * DIN * TT);
    uint32_t* sb32 = (uint32_t*)sbuf;
#pragma unroll
    for (int r = 0; r < 8; ++r) {
        int j = tid + r * PTHR;          // j < 4096
        float4 v = src[j];
        uint32_t pk = (v.x > 0.5f ? 1u : 0u)
                    | (v.y > 0.5f ? 1u : 0u) << 8
                    | (v.z > 0.5f ? 1u : 0u) << 16
                    | (v.w > 0.5f ? 1u : 0u) << 24;
        sb32[j] = pk;
    }
    __syncthreads();
#pragma unroll
    for (int u = tid; u < TT * (DIN / 16); u += PTHR) {
        int t = u >> 6, kseg = u & 63;
        uint32_t w[4];
#pragma unroll
        for (int q = 0; q < 4; ++q) {
            uint32_t b0 = (uint8_t)sbuf[(kseg * 16 + q * 4 + 0) * 16 + t];
            uint32_t b1 = (uint8_t)sbuf[(kseg * 16 + q * 4 + 1) * 16 + t];
            uint32_t b2 = (uint8_t)sbuf[(kseg * 16 + q * 4 + 2) * 16 + t];
            uint32_t b3 = (uint8_t)sbuf[(kseg * 16 + q * 4 + 3) * 16 + t];
            w[q] = b0 | (b1 << 8) | (b2 << 16) | (b3 << 24);
        }
        *(uint4*)(A + ((size_t)b * TT + t) * DIN + kseg * 16) =
            make_uint4(w[0], w[1], w[2], w[3]);
    }
}

// ---------------- fused exact-GEMM (R5 core: s8 IMMA, 3 limb planes per chunk) + BN + LIF ----------------
// CTA tile 128x128, 16 warps, each warp 32x32 x 3 planes. Trailing blocks do weight quant.
template<bool FINAL>
__global__ __launch_bounds__(NTHR, 1)
void gemm_lif(const int8_t* __restrict__ A,
              const int8_t* __restrict__ Wq,
              const float* __restrict__ bias, const float* __restrict__ gamma,
              const float* __restrict__ beta, const float* __restrict__ mmean,
              const float* __restrict__ mvar,
              int8_t* __restrict__ spk, float* __restrict__ out,
              int K, int N, int ntiles, int gx,
              const float* qsrc1, int8_t* qdst1, int qN1, int qK1, int qblk1,
              const float* qsrc2, int8_t* qdst2, int qN2, int qK2, int qblk2)
{
    const int bid = blockIdx.x;
    const int tid = threadIdx.x;

    if (bid >= ntiles) {               // folded weight-quant blocks (wave-2 slack fill)
        int e = bid - ntiles;
        if (e < qblk1) quant_range(qsrc1, qdst1, qN1, qK1, e, qblk1);
        else           quant_range(qsrc2, qdst2, qN2, qK2, e - qblk1, qblk2);
        return;
    }

    const int KP  = 3 * K;
    const int nsc = K / KCB;              // super-chunks
    constexpr int ABYTES = 128 * KCB;     // 16 KB A tile
    constexpr int PBYTES = 128 * KCB;     // 16 KB per B plane
    constexpr int STAGE  = ABYTES + 3 * PBYTES;   // 64 KB

    extern __shared__ __align__(16) char dsm[];
    char* sm = (char*)(((uintptr_t)dsm + 1023) & ~(uintptr_t)1023);
    const uint32_t sm32 = smem_u32(sm);

    const int wid   = tid >> 5;
    const int lane  = tid & 31;
    const int warpM = wid & 3;            // 4 M-groups of 32
    const int warpN = wid >> 2;           // 4 N-groups of 32
    const int m0    = (bid / gx) * 128;
    const int n0    = (bid % gx) * 128;

    int acc[3][2][4][4];                  // [plane][mf][nf][quad]
#pragma unroll
    for (int p = 0; p < 3; ++p)
#pragma unroll
        for (int i = 0; i < 2; ++i)
#pragma unroll
            for (int j = 0; j < 4; ++j)
#pragma unroll
                for (int q = 0; q < 4; ++q) acc[p][i][j][q] = 0;

    auto load_chunk = [&](int c) {
        const uint32_t sbase = sm32 + (uint32_t)(c % 3) * STAGE;
        const int8_t* gA = A + (size_t)m0 * K + c * KCB;
#pragma unroll
        for (int u = tid; u < 1024; u += NTHR) {
            int r = u >> 3, q = u & 7;
            cp16(sbase + SWZ((uint32_t)(r * 128 + q * 16)), gA + (size_t)r * K + q * 16);
        }
#pragma unroll
        for (int p = 0; p < 3; ++p) {
            const int8_t* gB = Wq + (size_t)n0 * KP + p * K + c * KCB;
            const uint32_t bbase = sbase + ABYTES + (uint32_t)p * PBYTES;
#pragma unroll
            for (int u = tid; u < 1024; u += NTHR) {
                int r = u >> 3, q = u & 7;
                cp16(bbase + SWZ((uint32_t)(r * 128 + q * 16)), gB + (size_t)r * KP + q * 16);
            }
        }
    };

    load_chunk(0); CP_COMMIT();
    if (nsc > 1) { load_chunk(1); CP_COMMIT(); }
    else         { CP_COMMIT(); }

    const int aRowB = warpM * 32 + (lane & 7) + ((lane >> 3) & 1) * 8;  // + mf*16
    const int aColB = ((lane >> 4) & 1) * 16;                           // + ks*32
    const int bRowB = warpN * 32 + (lane & 7) + ((lane >> 4) & 1) * 8;  // + bg*16
    const int bColB = ((lane >> 3) & 1) * 16;                           // + ks*32

    for (int i = 0; i < nsc; ++i) {
        CP_WAIT(1);
        __syncthreads();

        if (i + 2 < nsc) load_chunk(i + 2);
        CP_COMMIT();

        const uint32_t sA = sm32 + (uint32_t)(i % 3) * STAGE;
        const uint32_t sB = sA + ABYTES;

#pragma unroll
        for (int ks = 0; ks < 4; ++ks) {
            const int kb = ks * 32;
            uint32_t a[2][4];
#pragma unroll
            for (int mf = 0; mf < 2; ++mf)
                ldsm4(a[mf][0], a[mf][1], a[mf][2], a[mf][3],
                      sA + SWZ((uint32_t)((aRowB + mf * 16) * 128 + aColB + kb)));
#pragma unroll
            for (int p = 0; p < 3; ++p) {
                uint32_t b[2][4];
#pragma unroll
                for (int bg = 0; bg < 2; ++bg)
                    ldsm4(b[bg][0], b[bg][1], b[bg][2], b[bg][3],
                          sB + (uint32_t)p * PBYTES +
                          SWZ((uint32_t)((bRowB + bg * 16) * 128 + bColB + kb)));
#pragma unroll
                for (int mf = 0; mf < 2; ++mf)
#pragma unroll
                    for (int nf = 0; nf < 4; ++nf)
                        imma(acc[p][mf][nf], a[mf],
                             b[nf >> 1][(nf & 1) * 2], b[nf >> 1][(nf & 1) * 2 + 1]);
            }
        }
    }

    CP_WAIT(0);
    __syncthreads();   // stage buffers now reusable

    // ---- exact recombine: X = (l2*2^16 + l1*2^8 + l0) * 2^-27, single fp32 rounding ----
    float* scrF = (float*)sm;                          // [128][132]
    const double SL = 7.450580596923828125e-9;         // 2^-27
    const int r0w = warpM * 32 + (lane >> 2);
    const int c0w = warpN * 32 + (lane & 3) * 2;
#pragma unroll
    for (int mf = 0; mf < 2; ++mf) {
#pragma unroll
        for (int nf = 0; nf < 4; ++nf) {
            int r = r0w + mf * 16;
            int c = c0w + nf * 8;
            float x[4];
#pragma unroll
            for (int q = 0; q < 4; ++q) {
                double s = (double)acc[0][mf][nf][q] * 65536.0
                         + (double)acc[1][mf][nf][q] * 256.0
                         + (double)acc[2][mf][nf][q];
                x[q] = (float)(s * SL);
            }
            *(float2*)&scrF[r * 132 + c]       = make_float2(x[0], x[1]);
            *(float2*)&scrF[(r + 8) * 132 + c] = make_float2(x[2], x[3]);
        }
    }
    __syncthreads();

    // ---- BN + LIF (exact elementwise ops, bit-identical to reference semantics) ----
    int8_t* scrS = (int8_t*)(sm + 67584);              // [128][144]
#pragma unroll
    for (int task = tid; task < 1024; task += NTHR) {
        const int col = task & 127;
        const int bb  = task >> 7;
        const int n   = n0 + col;

        const float bo  = bias[n];
        const float ga  = gamma[n];
        const float be  = beta[n];
        const float mu  = mmean[n];
        const float var = mvar[n];
        const float den = sqrtf(__fadd_rn(var, 1e-5f));

        float v = 0.0f, sp = 0.0f, cnt = 0.0f;
#pragma unroll
        for (int t = 0; t < TT; ++t) {
            float x  = scrF[(bb * 16 + t) * 132 + col];
            float u  = __fsub_rn(__fadd_rn(x, bo), mu);
            float xn = __fadd_rn(__fdiv_rn(__fmul_rn(ga, u), den), be);
            v  = __fadd_rn(__fmul_rn(__fmul_rn(v, __fsub_rn(1.0f, sp)), 0.75f), xn);
            sp = (v > 0.5f) ? 1.0f : 0.0f;
            if (FINAL) cnt += sp;
            else       scrS[(bb * 16 + t) * 144 + col] = (int8_t)sp;
        }
        if (FINAL) {
            int bg = (m0 >> 4) + bb;
            out[(size_t)bg * N + n] = cnt * 0.0625f;
        }
    }

    if (!FINAL) {
        __syncthreads();
#pragma unroll
        for (int u = tid; u < 1024; u += NTHR) {
            int r = u >> 3, seg = u & 7;
            uint4 val = *(const uint4*)(scrS + r * 144 + seg * 16);
            *(uint4*)(spk + (size_t)(m0 + r) * N + n0 + seg * 16) = val;
        }
    }
}

// ---------------- host ----------------
extern "C" void kernel_launch(void* const* d_in, const int* in_sizes, int n_in,
                              void* d_out, int out_size)
{
    const float* spk_in = (const float*)d_in[0];
    const float* W0  = (const float*)d_in[1];
    const float* b0  = (const float*)d_in[2];
    const float* g0  = (const float*)d_in[3];
    const float* be0 = (const float*)d_in[4];
    const float* mm0 = (const float*)d_in[5];
    const float* mv0 = (const float*)d_in[6];
    const float* W1  = (const float*)d_in[7];
    const float* b1  = (const float*)d_in[8];
    const float* g1  = (const float*)d_in[9];
    const float* be1 = (const float*)d_in[10];
    const float* mm1 = (const float*)d_in[11];
    const float* mv1 = (const float*)d_in[12];
    const float* Wo  = (const float*)d_in[13];
    const float* bo  = (const float*)d_in[14];
    const float* go  = (const float*)d_in[15];
    const float* beo = (const float*)d_in[16];
    const float* mmo = (const float*)d_in[17];
    const float* mvo = (const float*)d_in[18];
    float* out = (float*)d_out;

    int8_t *A0, *s0, *s1, *W0q, *W1q, *Woq;
    cudaGetSymbolAddress((void**)&A0,  g_A0);
    cudaGetSymbolAddress((void**)&s0,  g_s0);
    cudaGetSymbolAddress((void**)&s1,  g_s1);
    cudaGetSymbolAddress((void**)&W0q, g_W0q);
    cudaGetSymbolAddress((void**)&W1q, g_W1q);
    cudaGetSymbolAddress((void**)&Woq, g_Woq);

    const int SMEM = 3 * (4 * 128 * KCB) + 1024;   // 3 x 64KB + align = 197632
    cudaFuncSetAttribute((const void*)gemm_lif<false>,
                         cudaFuncAttributeMaxDynamicSharedMemorySize, SMEM);
    cudaFuncSetAttribute((const void*)gemm_lif<true>,
                         cudaFuncAttributeMaxDynamicSharedMemorySize, SMEM);

    // prep: conv_in (128 blocks) + quant W0 (56 blocks) = 184 blocks, one wave
    prep_kernel<<<184, PTHR>>>(spk_in, A0, W0, W0q);

    // Layer 0: K=1024, N=2048; 256 tiles + 40 quant blocks (W1q, Woq).
    // Grid = 296 = exactly 2 x 148 SM waves: quant hides in wave-2 slack, NO third wave.
    {
        int gx = HH / 128, ntiles = gx * (MTOT / 128);   // 16 x 16 = 256
        gemm_lif<false><<<ntiles + 40, NTHR, SMEM>>>(
            A0, W0q, b0, g0, be0, mm0, mv0, s0, nullptr, DIN, HH, ntiles, gx,
            W1, W1q, HH, HH, 27,
            Wo, Woq, DOUT, HH, 13);
    }
    // Layer 1: K=2048, N=2048
    {
        int gx = HH / 128, ntiles = gx * (MTOT / 128);   // 256
        gemm_lif<false><<<ntiles, NTHR, SMEM>>>(
            s0, W1q, b1, g1, be1, mm1, mv1, s1, nullptr, HH, HH, ntiles, gx,
            nullptr, nullptr, 0, 1, 0, nullptr, nullptr, 0, 1, 0);
    }
    // Layer 2: K=2048, N=1024, final
    {
        int gx = DOUT / 128, ntiles = gx * (MTOT / 128); // 8 x 16 = 128
        gemm_lif<true><<<ntiles, NTHR, SMEM>>>(
            s1, Woq, bo, go, beo, mmo, mvo, nullptr, out, HH, DOUT, ntiles, gx,
            nullptr, nullptr, 0, 1, 0, nullptr, nullptr, 0, 1, 0);
    }
}

// round 14
// speedup vs baseline: 1.2309x; 1.2309x over previous
#include <cuda_runtime.h>
#include <cstdint>
#include <math.h>

#define TT   16
#define MTOT 2048
#define HH   2048
#define DIN  1024
#define DOUT 1024

#define NTHR 512
#define KCB  128          // int8 k per super-chunk (one 128B swizzle row)
#define NSM  148

// work item layout
#define IT_CONV0   0      // 64 items, 2 batches each
#define IT_Q0      64     // 16 items
#define IT_Q1      80     // 32 items
#define IT_QO      112    // 16 items
#define IT_L0      128    // 256 tiles (16 mt x 16 nt)
#define IT_L1      384    // 256 tiles
#define IT_L2      640    // 128 tiles (16 mt x 8 nt)
#define IT_TOTAL   768

// ---------------- static device scratch ----------------
__device__ __align__(1024) int8_t g_A0 [(size_t)MTOT * DIN];
__device__ __align__(1024) int8_t g_s0 [(size_t)MTOT * HH];
__device__ __align__(1024) int8_t g_s1 [(size_t)MTOT * HH];
__device__ __align__(1024) int8_t g_W0q[(size_t)HH   * 3 * DIN];
__device__ __align__(1024) int8_t g_W1q[(size_t)HH   * 3 * HH];
__device__ __align__(1024) int8_t g_Woq[(size_t)DOUT * 3 * HH];

struct SyncBlk {
    unsigned ticket;
    unsigned prep_done;      // conv(64) + qW0(16) -> 80
    unsigned q1_done;        // -> 32
    unsigned qo_done;        // -> 16
    unsigned l0row[16];      // each -> 16
    unsigned l1row[16];      // each -> 16
};
__device__ SyncBlk g_sync;

__global__ void zero_sync_kernel() {
    unsigned* p = (unsigned*)&g_sync;
    if (threadIdx.x < sizeof(SyncBlk) / 4) p[threadIdx.x] = 0;
}

// ---------------- helpers ----------------
__device__ __forceinline__ uint32_t smem_u32(const void* p) {
    uint32_t a;
    asm("{ .reg .u64 t; cvta.to.shared.u64 t, %1; cvt.u32.u64 %0, t; }" : "=r"(a) : "l"(p));
    return a;
}
__device__ __forceinline__ void cp16(uint32_t dst, const void* src) {
    asm volatile("cp.async.cg.shared.global [%0], [%1], 16;" :: "r"(dst), "l"(src));
}
#define CP_COMMIT() asm volatile("cp.async.commit_group;" ::: "memory")
#define CP_WAIT(n)  asm volatile("cp.async.wait_group %0;" :: "n"(n) : "memory")
#define SWZ(off) ((off) ^ (((off) >> 3) & 0x70))

__device__ __forceinline__ void ldsm4(uint32_t& r0, uint32_t& r1, uint32_t& r2, uint32_t& r3,
                                      uint32_t addr) {
    asm volatile("ldmatrix.sync.aligned.m8n8.x4.shared.b16 {%0,%1,%2,%3}, [%4];"
                 : "=r"(r0), "=r"(r1), "=r"(r2), "=r"(r3) : "r"(addr));
}
__device__ __forceinline__ void imma(int* d, const uint32_t* a, uint32_t b0, uint32_t b1) {
    asm volatile(
        "mma.sync.aligned.m16n8k32.row.col.s32.s8.s8.s32 "
        "{%0,%1,%2,%3}, {%4,%5,%6,%7}, {%8,%9}, {%0,%1,%2,%3};"
        : "+r"(d[0]), "+r"(d[1]), "+r"(d[2]), "+r"(d[3])
        : "r"(a[0]), "r"(a[1]), "r"(a[2]), "r"(a[3]), "r"(b0), "r"(b1));
}

// release: all threads fence, then one arrives
__device__ __forceinline__ void signal_done(unsigned* ctr) {
    __threadfence();
    __syncthreads();
    if (threadIdx.x == 0) atomicAdd(ctr, 1u);
}
// acquire: one thread polls, fence, barrier
__device__ __forceinline__ void wait_ge2(unsigned* c1, unsigned v1,
                                         unsigned* c2, unsigned v2) {
    if (threadIdx.x == 0) {
        while (*(volatile unsigned*)c1 < v1) __nanosleep(128);
        if (c2) while (*(volatile unsigned*)c2 < v2) __nanosleep(128);
        __threadfence();
    }
    __syncthreads();
}

// exact 3-limb int8 split of round(w*2^27): l2*2^16 + l1*2^8 + l0
__device__ void quant_range(const float* __restrict__ W,
                            int8_t* __restrict__ Wq,
                            int Nw, int K, int eblk, int nblk) {
    const int total4 = (Nw * K) >> 2;
    const int KP = 3 * K;
    for (int i4 = eblk * NTHR + threadIdx.x; i4 < total4; i4 += nblk * NTHR) {
        int idx = i4 << 2;
        int n = idx / K, k = idx - n * K;
        float4 w4 = *(const float4*)(W + idx);
        float wv[4] = {w4.x, w4.y, w4.z, w4.w};
        char l2v[4], l1v[4], l0v[4];
#pragma unroll
        for (int j = 0; j < 4; ++j) {
            long long wi = llrintf(wv[j] * 134217728.0f);   // 2^27
            int l0 = (int)((wi + 128) & 255) - 128;  wi = (wi - l0) >> 8;
            int l1 = (int)((wi + 128) & 255) - 128;  wi = (wi - l1) >> 8;
            l2v[j] = (char)wi; l1v[j] = (char)l1; l0v[j] = (char)l0;
        }
        size_t base = (size_t)n * KP + k;
        *(char4*)(Wq + base)         = make_char4(l2v[0], l2v[1], l2v[2], l2v[3]);
        *(char4*)(Wq + base + K)     = make_char4(l1v[0], l1v[1], l1v[2], l1v[3]);
        *(char4*)(Wq + base + 2 * K) = make_char4(l0v[0], l0v[1], l0v[2], l0v[3]);
    }
}

// conv one batch b: in[b][k][t] fp32 -> A[(b*16+t)][k] int8, via smem transpose
__device__ void conv_one(const float* __restrict__ in, int8_t* __restrict__ A,
                         int b, char* sm) {
    const int tid = threadIdx.x;
    int8_t* sbuf = (int8_t*)sm;          // [k][t], 16 KB
    uint32_t* sb32 = (uint32_t*)sbuf;
    const float4* src = (const float4*)(in + (size_t)b * DIN * TT);
#pragma unroll
    for (int r = 0; r < 8; ++r) {
        int j = tid + r * NTHR;          // j < 4096
        float4 v = src[j];
        uint32_t pk = (v.x > 0.5f ? 1u : 0u)
                    | (v.y > 0.5f ? 1u : 0u) << 8
                    | (v.z > 0.5f ? 1u : 0u) << 16
                    | (v.w > 0.5f ? 1u : 0u) << 24;
        sb32[j] = pk;
    }
    __syncthreads();
#pragma unroll
    for (int u = tid; u < TT * (DIN / 16); u += NTHR) {
        int t = u >> 6, kseg = u & 63;
        uint32_t w[4];
#pragma unroll
        for (int q = 0; q < 4; ++q) {
            uint32_t b0 = (uint8_t)sbuf[(kseg * 16 + q * 4 + 0) * 16 + t];
            uint32_t b1 = (uint8_t)sbuf[(kseg * 16 + q * 4 + 1) * 16 + t];
            uint32_t b2 = (uint8_t)sbuf[(kseg * 16 + q * 4 + 2) * 16 + t];
            uint32_t b3 = (uint8_t)sbuf[(kseg * 16 + q * 4 + 3) * 16 + t];
            w[q] = b0 | (b1 << 8) | (b2 << 16) | (b3 << 24);
        }
        *(uint4*)(A + ((size_t)b * TT + t) * DIN + kseg * 16) =
            make_uint4(w[0], w[1], w[2], w[3]);
    }
    __syncthreads();
}

// ---------------- one 128x128 tile: exact GEMM (R5 core) + BN + LIF ----------------
__device__ void tile_gemm_lif(const int8_t* __restrict__ A,
                              const int8_t* __restrict__ Wq,
                              const float* __restrict__ bias, const float* __restrict__ gamma,
                              const float* __restrict__ beta, const float* __restrict__ mmean,
                              const float* __restrict__ mvar,
                              int8_t* __restrict__ spk, float* __restrict__ out,
                              int K, int N, int m0, int n0, bool final_,
                              char* sm, uint32_t sm32)
{
    const int KP  = 3 * K;
    const int nsc = K / KCB;              // super-chunks (8 or 16)
    constexpr int ABYTES = 128 * KCB;     // 16 KB A tile
    constexpr int PBYTES = 128 * KCB;     // 16 KB per B plane
    constexpr int STAGE  = ABYTES + 3 * PBYTES;   // 64 KB

    const int tid   = threadIdx.x;
    const int wid   = tid >> 5;
    const int lane  = tid & 31;
    const int warpM = wid & 3;            // 4 M-groups of 32
    const int warpN = wid >> 2;           // 4 N-groups of 32

    int acc[3][2][4][4];                  // [plane][mf][nf][quad]
#pragma unroll
    for (int p = 0; p < 3; ++p)
#pragma unroll
        for (int i = 0; i < 2; ++i)
#pragma unroll
            for (int j = 0; j < 4; ++j)
#pragma unroll
                for (int q = 0; q < 4; ++q) acc[p][i][j][q] = 0;

    auto load_chunk = [&](int c) {
        const uint32_t sbase = sm32 + (uint32_t)(c % 3) * STAGE;
        const int8_t* gA = A + (size_t)m0 * K + c * KCB;
#pragma unroll
        for (int u = tid; u < 1024; u += NTHR) {
            int r = u >> 3, q = u & 7;
            cp16(sbase + SWZ((uint32_t)(r * 128 + q * 16)), gA + (size_t)r * K + q * 16);
        }
#pragma unroll
        for (int p = 0; p < 3; ++p) {
            const int8_t* gB = Wq + (size_t)n0 * KP + p * K + c * KCB;
            const uint32_t bbase = sbase + ABYTES + (uint32_t)p * PBYTES;
#pragma unroll
            for (int u = tid; u < 1024; u += NTHR) {
                int r = u >> 3, q = u & 7;
                cp16(bbase + SWZ((uint32_t)(r * 128 + q * 16)), gB + (size_t)r * KP + q * 16);
            }
        }
    };

    load_chunk(0); CP_COMMIT();
    load_chunk(1); CP_COMMIT();

    const int aRowB = warpM * 32 + (lane & 7) + ((lane >> 3) & 1) * 8;  // + mf*16
    const int aColB = ((lane >> 4) & 1) * 16;                           // + ks*32
    const int bRowB = warpN * 32 + (lane & 7) + ((lane >> 4) & 1) * 8;  // + bg*16
    const int bColB = ((lane >> 3) & 1) * 16;                           // + ks*32

    for (int i = 0; i < nsc; ++i) {
        CP_WAIT(1);
        __syncthreads();

        if (i + 2 < nsc) load_chunk(i + 2);
        CP_COMMIT();

        const uint32_t sA = sm32 + (uint32_t)(i % 3) * STAGE;
        const uint32_t sB = sA + ABYTES;

#pragma unroll
        for (int ks = 0; ks < 4; ++ks) {
            const int kb = ks * 32;
            uint32_t a[2][4];
#pragma unroll
            for (int mf = 0; mf < 2; ++mf)
                ldsm4(a[mf][0], a[mf][1], a[mf][2], a[mf][3],
                      sA + SWZ((uint32_t)((aRowB + mf * 16) * 128 + aColB + kb)));
#pragma unroll
            for (int p = 0; p < 3; ++p) {
                uint32_t b[2][4];
#pragma unroll
                for (int bg = 0; bg < 2; ++bg)
                    ldsm4(b[bg][0], b[bg][1], b[bg][2], b[bg][3],
                          sB + (uint32_t)p * PBYTES +
                          SWZ((uint32_t)((bRowB + bg * 16) * 128 + bColB + kb)));
#pragma unroll
                for (int mf = 0; mf < 2; ++mf)
#pragma unroll
                    for (int nf = 0; nf < 4; ++nf)
                        imma(acc[p][mf][nf], a[mf],
                             b[nf >> 1][(nf & 1) * 2], b[nf >> 1][(nf & 1) * 2 + 1]);
            }
        }
    }

    CP_WAIT(0);
    __syncthreads();   // stage buffers now reusable

    // ---- exact recombine: X = (l2*2^16 + l1*2^8 + l0) * 2^-27, single fp32 rounding ----
    float* scrF = (float*)sm;                          // [128][132]
    const double SL = 7.450580596923828125e-9;         // 2^-27
    const int r0w = warpM * 32 + (lane >> 2);
    const int c0w = warpN * 32 + (lane & 3) * 2;
#pragma unroll
    for (int mf = 0; mf < 2; ++mf) {
#pragma unroll
        for (int nf = 0; nf < 4; ++nf) {
            int r = r0w + mf * 16;
            int c = c0w + nf * 8;
            float x[4];
#pragma unroll
            for (int q = 0; q < 4; ++q) {
                double s = (double)acc[0][mf][nf][q] * 65536.0
                         + (double)acc[1][mf][nf][q] * 256.0
                         + (double)acc[2][mf][nf][q];
                x[q] = (float)(s * SL);
            }
            *(float2*)&scrF[r * 132 + c]       = make_float2(x[0], x[1]);
            *(float2*)&scrF[(r + 8) * 132 + c] = make_float2(x[2], x[3]);
        }
    }
    __syncthreads();

    // ---- BN + LIF (exact elementwise ops, bit-identical to reference semantics) ----
    int8_t* scrS = (int8_t*)(sm + 67584);              // [128][144]
#pragma unroll
    for (int task = tid; task < 1024; task += NTHR) {
        const int col = task & 127;
        const int bb  = task >> 7;
        const int n   = n0 + col;

        const float bo  = bias[n];
        const float ga  = gamma[n];
        const float be  = beta[n];
        const float mu  = mmean[n];
        const float var = mvar[n];
        const float den = sqrtf(__fadd_rn(var, 1e-5f));

        float v = 0.0f, sp = 0.0f, cnt = 0.0f;
#pragma unroll
        for (int t = 0; t < TT; ++t) {
            float x  = scrF[(bb * 16 + t) * 132 + col];
            float u  = __fsub_rn(__fadd_rn(x, bo), mu);
            float xn = __fadd_rn(__fdiv_rn(__fmul_rn(ga, u), den), be);
            v  = __fadd_rn(__fmul_rn(__fmul_rn(v, __fsub_rn(1.0f, sp)), 0.75f), xn);
            sp = (v > 0.5f) ? 1.0f : 0.0f;
            if (final_) cnt += sp;
            else        scrS[(bb * 16 + t) * 144 + col] = (int8_t)sp;
        }
        if (final_) {
            int bg = (m0 >> 4) + bb;
            out[(size_t)bg * N + n] = cnt * 0.0625f;
        }
    }

    if (!final_) {
        __syncthreads();
#pragma unroll
        for (int u = tid; u < 1024; u += NTHR) {
            int r = u >> 3, seg = u & 7;
            uint4 val = *(const uint4*)(scrS + r * 144 + seg * 16);
            *(uint4*)(spk + (size_t)(m0 + r) * N + n0 + seg * 16) = val;
        }
    }
}

// ---------------- persistent mega-kernel: work queue over all items ----------------
__global__ __launch_bounds__(NTHR, 1)
void mega_kernel(const float* __restrict__ spk_in,
                 const float* __restrict__ W0, const float* __restrict__ b0,
                 const float* __restrict__ g0, const float* __restrict__ be0,
                 const float* __restrict__ mm0, const float* __restrict__ mv0,
                 const float* __restrict__ W1, const float* __restrict__ b1,
                 const float* __restrict__ g1, const float* __restrict__ be1,
                 const float* __restrict__ mm1, const float* __restrict__ mv1,
                 const float* __restrict__ Wo, const float* __restrict__ bo,
                 const float* __restrict__ go, const float* __restrict__ beo,
                 const float* __restrict__ mmo, const float* __restrict__ mvo,
                 int8_t* __restrict__ A0, int8_t* __restrict__ s0, int8_t* __restrict__ s1,
                 int8_t* __restrict__ W0q, int8_t* __restrict__ W1q, int8_t* __restrict__ Woq,
                 float* __restrict__ out)
{
    extern __shared__ __align__(16) char dsm[];
    char* sm = (char*)(((uintptr_t)dsm + 1023) & ~(uintptr_t)1023);
    const uint32_t sm32 = smem_u32(sm);

    __shared__ unsigned s_item;

    for (;;) {
        if (threadIdx.x == 0) s_item = atomicAdd(&g_sync.ticket, 1u);
        __syncthreads();
        const unsigned item = s_item;
        if (item >= IT_TOTAL) break;

        if (item < IT_Q0) {
            // conv: 2 batches per item
            conv_one(spk_in, A0, 2 * item, sm);
            conv_one(spk_in, A0, 2 * item + 1, sm);
            signal_done(&g_sync.prep_done);
        } else if (item < IT_Q1) {
            quant_range(W0, W0q, HH, DIN, item - IT_Q0, 16);
            signal_done(&g_sync.prep_done);
        } else if (item < IT_QO) {
            quant_range(W1, W1q, HH, HH, item - IT_Q1, 32);
            signal_done(&g_sync.q1_done);
        } else if (item < IT_L0) {
            quant_range(Wo, Woq, DOUT, HH, item - IT_QO, 16);
            signal_done(&g_sync.qo_done);
        } else if (item < IT_L1) {
            const int e = item - IT_L0, mt = e >> 4, nt = e & 15;
            wait_ge2(&g_sync.prep_done, 80, nullptr, 0);
            tile_gemm_lif(A0, W0q, b0, g0, be0, mm0, mv0, s0, nullptr,
                          DIN, HH, mt * 128, nt * 128, false, sm, sm32);
            signal_done(&g_sync.l0row[mt]);
        } else if (item < IT_L2) {
            const int e = item - IT_L1, mt = e >> 4, nt = e & 15;
            wait_ge2(&g_sync.q1_done, 32, &g_sync.l0row[mt], 16);
            tile_gemm_lif(s0, W1q, b1, g1, be1, mm1, mv1, s1, nullptr,
                          HH, HH, mt * 128, nt * 128, false, sm, sm32);
            signal_done(&g_sync.l1row[mt]);
        } else {
            const int e = item - IT_L2, mt = e >> 3, nt = e & 7;
            wait_ge2(&g_sync.qo_done, 16, &g_sync.l1row[mt], 16);
            tile_gemm_lif(s1, Woq, bo, go, beo, mmo, mvo, nullptr, out,
                          HH, DOUT, mt * 128, nt * 128, true, sm, sm32);
        }
        __syncthreads();   // smem quiescent before next item
    }
}

// ---------------- host ----------------
extern "C" void kernel_launch(void* const* d_in, const int* in_sizes, int n_in,
                              void* d_out, int out_size)
{
    const float* spk_in = (const float*)d_in[0];
    const float* W0  = (const float*)d_in[1];
    const float* b0  = (const float*)d_in[2];
    const float* g0  = (const float*)d_in[3];
    const float* be0 = (const float*)d_in[4];
    const float* mm0 = (const float*)d_in[5];
    const float* mv0 = (const float*)d_in[6];
    const float* W1  = (const float*)d_in[7];
    const float* b1  = (const float*)d_in[8];
    const float* g1  = (const float*)d_in[9];
    const float* be1 = (const float*)d_in[10];
    const float* mm1 = (const float*)d_in[11];
    const float* mv1 = (const float*)d_in[12];
    const float* Wo  = (const float*)d_in[13];
    const float* bo  = (const float*)d_in[14];
    const float* go  = (const float*)d_in[15];
    const float* beo = (const float*)d_in[16];
    const float* mmo = (const float*)d_in[17];
    const float* mvo = (const float*)d_in[18];
    float* out = (float*)d_out;

    int8_t *A0, *s0, *s1, *W0q, *W1q, *Woq;
    cudaGetSymbolAddress((void**)&A0,  g_A0);
    cudaGetSymbolAddress((void**)&s0,  g_s0);
    cudaGetSymbolAddress((void**)&s1,  g_s1);
    cudaGetSymbolAddress((void**)&W0q, g_W0q);
    cudaGetSymbolAddress((void**)&W1q, g_W1q);
    cudaGetSymbolAddress((void**)&Woq, g_Woq);

    const int SMEM = 3 * (4 * 128 * KCB) + 1024;   // 3 x 64KB + align = 197632
    cudaFuncSetAttribute((const void*)mega_kernel,
                         cudaFuncAttributeMaxDynamicSharedMemorySize, SMEM);

    zero_sync_kernel<<<1, 64>>>();
    mega_kernel<<<NSM, NTHR, SMEM>>>(spk_in,
        W0, b0, g0, be0, mm0, mv0,
        W1, b1, g1, be1, mm1, mv1,
        Wo, bo, go, beo, mmo, mvo,
        A0, s0, s1, W0q, W1q, Woq, out);
}